// round 6
// baseline (speedup 1.0000x reference)
#include <cuda_runtime.h>
#include <stdint.h>

#define BN 4096
#define DD 128
#define EPSF 1e-6f
#define NWORDS (BN/32)        // 128 words per row
#define PART 512              // 32 j-tiles * 16 tx partials per row
#define TK 32                 // K chunk

// ---------------- device scratch (static; no allocations allowed) ----------
__device__ float g_sq[BN];
__device__ float g_s[BN];
__device__ unsigned g_posbits[BN * NWORDS];
__device__ unsigned g_negbits[BN * NWORDS];
__device__ unsigned long long g_posPart[(size_t)BN * PART];
__device__ unsigned long long g_negPart[(size_t)BN * PART];
__device__ float g_loss[BN];
__device__ float g_w[BN];

// ---------------- kernel 1: row sums + bit-packed permuted masks -----------
// Masks arrive as 4-byte elements (bool -> int32 or float32 by the harness).
// Nonzero 32-bit word <=> true, valid for both encodings.
__global__ void prep_kernel(const float* __restrict__ E,
                            const int* __restrict__ tgt,
                            const unsigned* __restrict__ P,
                            const unsigned* __restrict__ N)
{
    int i = blockIdx.x;
    int t = threadIdx.x;            // 128 threads

    // s[i], sq[i]
    float v = E[(size_t)i * DD + t];
    float s = v, q = v * v;
    #pragma unroll
    for (int o = 16; o; o >>= 1) {
        s += __shfl_down_sync(0xffffffffu, s, o);
        q += __shfl_down_sync(0xffffffffu, q, o);
    }
    __shared__ float ss[4], qq[4];
    if ((t & 31) == 0) { ss[t >> 5] = s; qq[t >> 5] = q; }
    __syncthreads();
    if (t == 0) {
        g_s[i]  = ss[0] + ss[1] + ss[2] + ss[3];
        g_sq[i] = qq[0] + qq[1] + qq[2] + qq[3];
    }

    // bit-pack permuted masks: bit u of word t = mask[i][target_idx[t*32+u]]
    const unsigned* Pi = P + (size_t)i * BN;
    const unsigned* Ni = N + (size_t)i * BN;
    unsigned pm = 0u, nm = 0u;
    int base = t * 32;
    #pragma unroll 8
    for (int u = 0; u < 32; u++) {
        int tj = tgt[base + u];
        pm |= (Pi[tj] != 0u ? 1u : 0u) << u;
        nm |= (Ni[tj] != 0u ? 1u : 0u) << u;
    }
    g_posbits[i * NWORDS + t] = pm;
    g_negbits[i * NWORDS + t] = nm;
}

// ---------------- kernel 2: tiled SGEMM + masked argmax/argmin epilogue ----
__global__ __launch_bounds__(256)
void main_kernel(const float* __restrict__ E)
{
    __shared__ float As[TK][132];   // [k][i]
    __shared__ float Bs[TK][132];   // [k][j]
    __shared__ float sSqI[128], sSI[128], sSqJ[128], sSJ[128];
    __shared__ unsigned smPos[128][4], smNeg[128][4];

    const int tid = threadIdx.x;
    const int tx = tid & 15;        // j direction
    const int ty = tid >> 4;        // i direction
    const int j0 = blockIdx.x * 128;
    const int i0 = blockIdx.y * 128;

    if (tid < 128) {
        sSqI[tid] = g_sq[i0 + tid]; sSI[tid] = g_s[i0 + tid];
        sSqJ[tid] = g_sq[j0 + tid]; sSJ[tid] = g_s[j0 + tid];
    }
    const int wbase = j0 >> 5;      // first mask word for this j-tile
    for (int m = tid; m < 512; m += 256) {
        int r = m >> 2, w = m & 3;
        smPos[r][w] = g_posbits[(i0 + r) * NWORDS + wbase + w];
        smNeg[r][w] = g_negbits[(i0 + r) * NWORDS + wbase + w];
    }

    float acc[8][8];
    #pragma unroll
    for (int r = 0; r < 8; r++)
        #pragma unroll
        for (int c = 0; c < 8; c++) acc[r][c] = 0.0f;

    for (int kk = 0; kk < DD; kk += TK) {
        __syncthreads();
        // load + transpose chunk: 128 rows x TK k, both tiles
        #pragma unroll
        for (int p = 0; p < 4; p++) {
            int f = tid + p * 256;          // 0..1023
            int row = f >> 3;               // 0..127
            int k4 = (f & 7) * 4;           // 0..28
            float4 va = *(const float4*)(E + (size_t)(i0 + row) * DD + kk + k4);
            As[k4 + 0][row] = va.x; As[k4 + 1][row] = va.y;
            As[k4 + 2][row] = va.z; As[k4 + 3][row] = va.w;
            float4 vb = *(const float4*)(E + (size_t)(j0 + row) * DD + kk + k4);
            Bs[k4 + 0][row] = vb.x; Bs[k4 + 1][row] = vb.y;
            Bs[k4 + 2][row] = vb.z; Bs[k4 + 3][row] = vb.w;
        }
        __syncthreads();
        #pragma unroll
        for (int k = 0; k < TK; k++) {
            float4 a0 = *(const float4*)(&As[k][ty * 8]);
            float4 a1 = *(const float4*)(&As[k][ty * 8 + 4]);
            float4 b0 = *(const float4*)(&Bs[k][tx * 8]);
            float4 b1 = *(const float4*)(&Bs[k][tx * 8 + 4]);
            float a[8] = {a0.x, a0.y, a0.z, a0.w, a1.x, a1.y, a1.z, a1.w};
            float b[8] = {b0.x, b0.y, b0.z, b0.w, b1.x, b1.y, b1.z, b1.w};
            #pragma unroll
            for (int r = 0; r < 8; r++)
                #pragma unroll
                for (int c = 0; c < 8; c++)
                    acc[r][c] = fmaf(a[r], b[c], acc[r][c]);
        }
    }

    // epilogue: distances + masked argmax/argmin partials
    const float deps = (float)DD * (EPSF * EPSF);
    #pragma unroll
    for (int r = 0; r < 8; r++) {
        int li = ty * 8 + r;
        float sqi = sSqI[li], si = sSI[li];
        unsigned pw = smPos[li][tx >> 2];
        unsigned nw = smNeg[li][tx >> 2];
        unsigned long long bp = 0ull;
        unsigned long long bn = 0xFFFFFFFFFFFFFFFFull;
        #pragma unroll
        for (int c = 0; c < 8; c++) {
            int jl = tx * 8 + c;
            float d2 = sqi + sSqJ[jl] - 2.0f * acc[r][c]
                     + 2.0f * EPSF * (si - sSJ[jl]) + deps;
            float dmv = sqrtf(fmaxf(d2, 0.0f));
            unsigned bits = __float_as_uint(dmv);   // dm >= 0 -> bits monotonic
            unsigned j = (unsigned)(j0 + jl);
            if ((pw >> (jl & 31)) & 1u) {
                unsigned long long pk = ((unsigned long long)bits << 32) | (~j);
                if (pk > bp) bp = pk;               // ties: smaller j wins (~j larger)
            }
            if ((nw >> (jl & 31)) & 1u) {
                unsigned long long pk = ((unsigned long long)bits << 32) | j;
                if (pk < bn) bn = pk;               // ties: smaller j wins
            }
        }
        size_t gi = (size_t)(i0 + li);
        g_posPart[gi * PART + blockIdx.x * 16 + tx] = bp;
        g_negPart[gi * PART + blockIdx.x * 16 + tx] = bn;
    }
}

// ---------------- kernel 3: per-row reduce + exact triplet loss ------------
__global__ void row_kernel(const float* __restrict__ E)
{
    int i = blockIdx.x;
    int t = threadIdx.x;            // 128 threads

    unsigned long long bp = 0ull, bn = 0xFFFFFFFFFFFFFFFFull;
    for (int p = t; p < PART; p += 128) {
        unsigned long long a = g_posPart[(size_t)i * PART + p]; if (a > bp) bp = a;
        unsigned long long b = g_negPart[(size_t)i * PART + p]; if (b < bn) bn = b;
    }
    #pragma unroll
    for (int o = 16; o; o >>= 1) {
        unsigned long long a = __shfl_down_sync(0xffffffffu, bp, o); if (a > bp) bp = a;
        unsigned long long b = __shfl_down_sync(0xffffffffu, bn, o); if (b < bn) bn = b;
    }
    __shared__ unsigned long long sp[4], sn[4], shP, shN;
    if ((t & 31) == 0) { sp[t >> 5] = bp; sn[t >> 5] = bn; }
    __syncthreads();
    if (t == 0) {
        bp = sp[0]; bn = sn[0];
        for (int w = 1; w < 4; w++) { if (sp[w] > bp) bp = sp[w]; if (sn[w] < bn) bn = sn[w]; }
        shP = bp; shN = bn;
    }
    __syncthreads();
    bp = shP; bn = shN;

    if (bp == 0ull || bn == 0xFFFFFFFFFFFFFFFFull) {   // invalid row
        if (t == 0) { g_loss[i] = 0.0f; g_w[i] = 0.0f; }
        return;
    }
    int pi = (int)(~(unsigned)bp) & (BN - 1);   // undo ~j
    int ni = (int)((unsigned)bn);

    float av = E[(size_t)i  * DD + t];
    float pv = E[(size_t)pi * DD + t];
    float nv = E[(size_t)ni * DD + t];
    float d1 = av - pv + EPSF;
    float d2 = av - nv + EPSF;
    float d3 = pv - nv + EPSF;
    float s1 = d1 * d1, s2 = d2 * d2, s3 = d3 * d3;
    #pragma unroll
    for (int o = 16; o; o >>= 1) {
        s1 += __shfl_down_sync(0xffffffffu, s1, o);
        s2 += __shfl_down_sync(0xffffffffu, s2, o);
        s3 += __shfl_down_sync(0xffffffffu, s3, o);
    }
    __shared__ float r1[4], r2[4], r3[4];
    if ((t & 31) == 0) { r1[t >> 5] = s1; r2[t >> 5] = s2; r3[t >> 5] = s3; }
    __syncthreads();
    if (t == 0) {
        float S1 = r1[0] + r1[1] + r1[2] + r1[3];
        float S2 = r2[0] + r2[1] + r2[2] + r2[3];
        float S3 = r3[0] + r3[1] + r3[2] + r3[3];
        float ap = sqrtf(S1), an = sqrtf(S2), pn = sqrtf(S3);
        float loss = fmaxf(ap - fminf(an, pn) + 1.0f, 0.0f);
        g_loss[i] = loss;
        g_w[i] = 1.0f;
    }
}

// ---------------- kernel 4: deterministic scalar reduction -----------------
__global__ void final_kernel(float* __restrict__ out)
{
    int t = threadIdx.x;            // 1024 threads
    float ls = 0.0f, ws = 0.0f;
    for (int r = t; r < BN; r += 1024) { ls += g_loss[r]; ws += g_w[r]; }
    #pragma unroll
    for (int o = 16; o; o >>= 1) {
        ls += __shfl_down_sync(0xffffffffu, ls, o);
        ws += __shfl_down_sync(0xffffffffu, ws, o);
    }
    __shared__ float sl[32], sw[32];
    if ((t & 31) == 0) { sl[t >> 5] = ls; sw[t >> 5] = ws; }
    __syncthreads();
    if (t == 0) {
        float L = 0.0f, W = 0.0f;
        for (int w = 0; w < 32; w++) { L += sl[w]; W += sw[w]; }
        out[0] = L / fmaxf(W, 1.0f);
    }
}

// ---------------- launch ----------------------------------------------------
extern "C" void kernel_launch(void* const* d_in, const int* in_sizes, int n_in,
                              void* d_out, int out_size)
{
    const float*    E   = (const float*)d_in[0];
    const int*      tgt = (const int*)d_in[1];
    const unsigned* P   = (const unsigned*)d_in[2];
    const unsigned* N   = (const unsigned*)d_in[3];
    float* out = (float*)d_out;

    prep_kernel<<<BN, 128>>>(E, tgt, P, N);
    dim3 grid(32, 32);
    main_kernel<<<grid, 256>>>(E);
    row_kernel<<<BN, 128>>>(E);
    final_kernel<<<1, 1024>>>(out);
}